// round 14
// baseline (speedup 1.0000x reference)
#include <cuda_runtime.h>
#include <cuda_fp16.h>
#include <math.h>
#include <stdint.h>

#define BATCH 4
#define RAYS  8192
#define NRAYS (BATCH*RAYS)          // 32768
#define NS    48
#define RES   48
#define CH    32
#define NPTS  (NRAYS*NS)            // 1572864
#define NTILES (NPTS/128)           // 12288
#define NCHUNKS (NTILES/3)          // 4096 chunks of 3 tiles = 8 rays

#define DT    0.03125f

// ---------------- device scratch ----------------
__device__ __align__(16) __half g_mat_h[3*BATCH*RES*RES*CH];
__device__ __align__(16) __half g_vec_h[3*BATCH*RES*CH];
__device__ __align__(16) float  g_rgb[(size_t)NPTS*3];
__device__ __align__(16) float  g_bias[(size_t)NRAYS*64];

__device__ __forceinline__ float tanh_apx(float x) {
    float r;
    asm("tanh.approx.f32 %0, %1;" : "=f"(r) : "f"(x));
    return r;
}

__device__ __forceinline__ float gelu_fast(float x) {
    float inner = 0.7978845608f * x * fmaf(0.044715f * x, x, 1.0f);
    return 0.5f * x * (1.0f + tanh_apx(inner));
}

__device__ __forceinline__ float sigmoid_fast(float x) {
    return 0.5f * (1.0f + tanh_apx(0.5f * x));
}

__device__ __forceinline__ __half2 gelu_h2(__half2 x) {
    const __half2 K2  = __float2half2_rn(0.035677408f);
    const __half2 K0  = __float2half2_rn(0.7978845608f);
    const __half2 H05 = __float2half2_rn(0.5f);
    __half2 x2 = __hmul2(x, x);
    __half2 inner = __hmul2(x, __hfma2(x2, K2, K0));
    uint32_t ti;
    asm("tanh.approx.f16x2 %0, %1;" : "=r"(ti) : "r"(*(uint32_t*)&inner));
    __half2 th = *(__half2*)&ti;
    __half2 h = __hmul2(x, H05);
    return __hfma2(h, th, h);
}

__device__ __forceinline__ void mma_f16(float d[4],
                                        uint32_t a0, uint32_t a1, uint32_t a2, uint32_t a3,
                                        uint32_t b0, uint32_t b1) {
    asm volatile("mma.sync.aligned.m16n8k16.row.col.f32.f16.f16.f32 "
                 "{%0,%1,%2,%3}, {%4,%5,%6,%7}, {%8,%9}, {%0,%1,%2,%3};"
                 : "+f"(d[0]), "+f"(d[1]), "+f"(d[2]), "+f"(d[3])
                 : "r"(a0), "r"(a1), "r"(a2), "r"(a3), "r"(b0), "r"(b1));
}

__device__ __forceinline__ void ldsm_x4(uint32_t& r0, uint32_t& r1, uint32_t& r2, uint32_t& r3,
                                        uint32_t saddr) {
    asm volatile("ldmatrix.sync.aligned.m8n8.x4.shared.b16 {%0,%1,%2,%3}, [%4];"
                 : "=r"(r0), "=r"(r1), "=r"(r2), "=r"(r3) : "r"(saddr));
}

__device__ __forceinline__ uint32_t pack_h2(float lo, float hi) {
    __half2 h = __floats2half2_rn(lo, hi);
    return *(uint32_t*)&h;
}

// ---------------- prep: transposes to channel-last fp16 ----------------
__global__ void k_transpose_mat(const float* __restrict__ m) {
    int idx = blockIdx.x * blockDim.x + threadIdx.x;
    if (idx >= 3*BATCH*RES*RES*CH) return;
    int c   = idx % CH;
    int pix = (idx / CH) % (RES*RES);
    int ib  = idx / (CH*RES*RES);
    g_mat_h[idx] = __float2half_rn(m[((size_t)ib*CH + c)*(RES*RES) + pix]);
}

__global__ void k_transpose_vec(const float* __restrict__ v) {
    int idx = blockIdx.x * blockDim.x + threadIdx.x;
    if (idx >= 3*BATCH*RES*CH) return;
    int c  = idx % CH;
    int r  = (idx / CH) % RES;
    int ib = idx / (CH*RES);
    g_vec_h[idx] = __float2half_rn(v[((size_t)ib*CH + c)*RES + r]);
}

__global__ void k_bias(const float* __restrict__ rays_d,
                       const float* __restrict__ w1, const float* __restrict__ b1) {
    int q = blockIdx.x * blockDim.x + threadIdx.x;
    if (q >= NRAYS) return;
    float dx = rays_d[q*3+0], dy = rays_d[q*3+1], dz = rays_d[q*3+2];
    float inv = 1.0f / sqrtf(dx*dx + dy*dy + dz*dz);
    dx *= inv; dy *= inv; dz *= inv;
    float pe[27];
    pe[0] = dx; pe[1] = dy; pe[2] = dz;
    float f = 1.0f;
    #pragma unroll
    for (int fi = 0; fi < 4; fi++) {
        float s, c;
        sincosf(dx*f, &s, &c); pe[3 + fi*3 + 0] = s; pe[15 + fi*3 + 0] = c;
        sincosf(dy*f, &s, &c); pe[3 + fi*3 + 1] = s; pe[15 + fi*3 + 1] = c;
        sincosf(dz*f, &s, &c); pe[3 + fi*3 + 2] = s; pe[15 + fi*3 + 2] = c;
        f *= 2.0f;
    }
    float acc[64];
    #pragma unroll
    for (int j = 0; j < 64; j++) acc[j] = b1[j];
    #pragma unroll 1
    for (int k = 0; k < 27; k++) {
        float v = pe[k];
        const float* wr = w1 + (64 + k) * 64;
        #pragma unroll
        for (int j = 0; j < 64; j++) acc[j] += v * wr[j];
    }
    float* o = g_bias + (size_t)q * 64;
    #pragma unroll
    for (int j = 0; j < 64; j++) o[j] = acc[j];
}

// ---------------- fused persistent, double-buffered, chunked render -------------
#define F_PITCH 88
#define F_BUF_FLOATS (128*F_PITCH/2)      // 5632
#define F_BUF_BYTES  (F_BUF_FLOATS*4)     // 22528
#define OF_B1   (2*F_BUF_FLOATS)          // 11264
#define OF_B2   (OF_B1 + 5*4*136)         // +2720 -> 13984
#define OF_W2   (OF_B2 + 4*4*136)         // +2176 -> 16160
#define OF_BM   (OF_W2 + 192)             // 16352
#define OF_BIAS (OF_BM + 64)              // 16416, 2 x 256 floats
#define SMEM_FLOATS (OF_BIAS + 512)       // 16928 floats = 67712 B

__global__ __launch_bounds__(256, 2)
void k_fused(const float* __restrict__ rays_o, const float* __restrict__ rays_d,
             const float* __restrict__ w_mat, const float* __restrict__ b_mat,
             const float* __restrict__ w1, const float* __restrict__ w2,
             const float* __restrict__ b2,
             float* __restrict__ out_rgb, float* __restrict__ out_depth,
             float* __restrict__ out_sigma) {
    extern __shared__ float sm[];
    float* sB1   = sm + OF_B1;
    float* sB2   = sm + OF_B2;
    float* sW2   = sm + OF_W2;
    float* sBm   = sm + OF_BM;
    float* sBias = sm + OF_BIAS;

    const int tid  = threadIdx.x;
    const int lane = tid & 31;
    const int wid  = tid >> 5;
    const int q    = lane & 3;
    const int g    = lane >> 2;

    // zero pad cols 72..79 of BOTH F buffers (never written again)
    {
        int bufr = tid >> 7, row = tid & 127;
        *(uint4*)((__half*)sm + bufr*F_BUF_FLOATS*2 + row*F_PITCH + 72) = make_uint4(0,0,0,0);
    }

    // ---- one-time fp16 weight packing (hi only) ----
    for (int i = tid; i < 5*4*64; i += 256) {
        int kb = i >> 8, qq = (i >> 6) & 3, n = i & 63;
        int k0 = kb*16 + 2*qq;
        float v0 = w_mat[k0*64 + n];
        float v1 = w_mat[(k0+1)*64 + n];
        float v2 = (k0+8 < 72) ? w_mat[(k0+8)*64 + n] : 0.0f;
        float v3 = (k0+9 < 72) ? w_mat[(k0+9)*64 + n] : 0.0f;
        uint2 e;
        e.x = pack_h2(v0, v1);
        e.y = pack_h2(v2, v3);
        *(uint2*)(sB1 + (kb*4 + qq)*136 + n*2) = e;
    }
    for (int i = tid; i < 4*4*64; i += 256) {
        int kb = i >> 8, qq = (i >> 6) & 3, n = i & 63;
        int k0 = kb*16 + 2*qq;
        uint2 e;
        e.x = pack_h2(w1[k0*64 + n],     w1[(k0+1)*64 + n]);
        e.y = pack_h2(w1[(k0+8)*64 + n], w1[(k0+9)*64 + n]);
        *(uint2*)(sB2 + (kb*4 + qq)*136 + n*2) = e;
    }
    if (tid < 192) sW2[tid] = w2[tid];
    if (tid < 64)  sBm[tid] = b_mat[tid];
    __syncthreads();

    const int m0 = wid * 16;
    const int lp   = tid >> 1;      // local point row (0..127)
    const int csel = tid & 1;       // 0: chunks 0,1   1: chunks 2,3

    const uint32_t sF_sh0 = (uint32_t)__cvta_generic_to_shared((__half*)sm);
    const uint32_t a_base0 = sF_sh0 +
        (uint32_t)(((m0 + (lane & 15)) * F_PITCH + ((lane >> 4) * 8)) * 2);

    int buf = 0;
    #pragma unroll 1
    for (int chunk = blockIdx.x; chunk < NCHUNKS; chunk += gridDim.x) {
        // 3 tiles per chunk = 8 whole rays [chunk*8, chunk*8+8)
        #pragma unroll 1
        for (int ti = 0; ti < 3; ti++, buf ^= 1) {
            const int tile  = chunk*3 + ti;
            const int pbase = tile * 128;
            __half* sF     = (__half*)sm + buf * F_BUF_FLOATS * 2;
            float*  sBiasB = sBias + buf * 256;
            const int ray0 = pbase / NS;

            // ---- stage per-ray bias (<=4 rays per 128-pt tile) ----
            {
                int row = tid >> 6, col = tid & 63;
                int r = ray0 + row;
                if (r > NRAYS-1) r = NRAYS-1;
                sBiasB[row*64 + col] = g_bias[(size_t)r*64 + col];
            }

            // ============ sampling phase: 2 adjacent threads per point =========
            {
                const int p   = pbase + lp;
                const int s   = p % NS;
                const int ray = p / NS;
                const int b   = ray / RAYS;

                const float ox = rays_o[ray*3+0], oy = rays_o[ray*3+1], oz = rays_o[ray*3+2];
                const float dx = rays_d[ray*3+0], dy = rays_d[ray*3+1], dz = rays_d[ray*3+2];
                const float t  = ((float)s + 0.5f) * DT;

                const float px = ((ox + dx*t) + 0.8f) * 1.25f - 1.0f;
                const float py = ((oy + dy*t) + 0.8f) * 1.25f - 1.0f;
                const float pz = ((oz + dz*t) + 0.8f) * 1.25f - 1.0f;

                float sigma = 0.0f;
                __half* fo = sF + lp*F_PITCH;
                const int cc0 = csel*2;

                #pragma unroll 1
                for (int pl = 0; pl < 3; pl++) {
                    const float cx = (pl == 0) ? px : ((pl == 1) ? pz : py);
                    const float cy = (pl == 0) ? py : ((pl == 1) ? px : pz);
                    const float cz = (pl == 0) ? pz : ((pl == 1) ? py : px);

                    const float fx = (cx + 1.0f) * 23.5f;
                    const float fy = (cy + 1.0f) * 23.5f;
                    const float fz = (cz + 1.0f) * 23.5f;
                    const float x0f = floorf(fx), y0f = floorf(fy), z0f = floorf(fz);
                    const float wx = fx - x0f, wy = fy - y0f, wz = fz - z0f;
                    const int ix0 = (int)x0f, iy0 = (int)y0f, iz0 = (int)z0f;

                    const float mx0 = (ix0 >= 0  && ix0 <  RES)   ? 1.0f : 0.0f;
                    const float mx1 = (ix0 >= -1 && ix0 <  RES-1) ? 1.0f : 0.0f;
                    const float my0 = (iy0 >= 0  && iy0 <  RES)   ? 1.0f : 0.0f;
                    const float my1 = (iy0 >= -1 && iy0 <  RES-1) ? 1.0f : 0.0f;
                    const float mz0 = (iz0 >= 0  && iz0 <  RES)   ? 1.0f : 0.0f;
                    const float mz1 = (iz0 >= -1 && iz0 <  RES-1) ? 1.0f : 0.0f;

                    const int cx0 = min(max(ix0,   0), RES-1), cx1 = min(max(ix0+1, 0), RES-1);
                    const int cy0 = min(max(iy0,   0), RES-1), cy1 = min(max(iy0+1, 0), RES-1);
                    const int cz0 = min(max(iz0,   0), RES-1), cz1 = min(max(iz0+1, 0), RES-1);

                    const float w00 = (1.0f-wx)*(1.0f-wy)*mx0*my0;
                    const float w10 = wx*(1.0f-wy)*mx1*my0;
                    const float w01 = (1.0f-wx)*wy*mx0*my1;
                    const float w11 = wx*wy*mx1*my1;
                    const float u0  = (1.0f-wz)*mz0;
                    const float u1  = wz*mz1;

                    const __half* mb = g_mat_h + ((size_t)(pl*BATCH + b) * (RES*RES)) * CH;
                    const __half* vb = g_vec_h + ((size_t)(pl*BATCH + b) * RES) * CH;
                    const uint4* p00 = (const uint4*)(mb + (size_t)(cy0*RES + cx0) * CH);
                    const uint4* p10 = (const uint4*)(mb + (size_t)(cy0*RES + cx1) * CH);
                    const uint4* p01 = (const uint4*)(mb + (size_t)(cy1*RES + cx0) * CH);
                    const uint4* p11 = (const uint4*)(mb + (size_t)(cy1*RES + cx1) * CH);
                    const uint4* q0  = (const uint4*)(vb + (size_t)cz0 * CH);
                    const uint4* q1  = (const uint4*)(vb + (size_t)cz1 * CH);

                    const __half2 W00 = __float2half2_rn(w00);
                    const __half2 W10 = __float2half2_rn(w10);
                    const __half2 W01 = __float2half2_rn(w01);
                    const __half2 W11 = __float2half2_rn(w11);
                    const __half2 U0  = __float2half2_rn(u0);
                    const __half2 U1  = __float2half2_rn(u1);

                    #pragma unroll
                    for (int ci = 0; ci < 2; ci++) {
                        const int cc = cc0 + ci;
                        uint4 ua = p00[cc], ub = p10[cc], uc = p01[cc], ud = p11[cc];
                        uint4 ue = q0[cc],  uf = q1[cc];
                        const __half2* ha = (const __half2*)&ua;
                        const __half2* hb = (const __half2*)&ub;
                        const __half2* hc = (const __half2*)&uc;
                        const __half2* hd = (const __half2*)&ud;
                        const __half2* he = (const __half2*)&ue;
                        const __half2* hf = (const __half2*)&uf;
                        if (cc == 0) {
                            #pragma unroll
                            for (int j = 0; j < 4; j++) {
                                float2 fa = __half22float2(ha[j]);
                                float2 fb = __half22float2(hb[j]);
                                float2 fc = __half22float2(hc[j]);
                                float2 fd = __half22float2(hd[j]);
                                float2 fe = __half22float2(he[j]);
                                float2 ff = __half22float2(hf[j]);
                                float pf0 = w00*fa.x + w10*fb.x + w01*fc.x + w11*fd.x;
                                float pf1 = w00*fa.y + w10*fb.y + w01*fc.y + w11*fd.y;
                                float lf0 = u0*fe.x + u1*ff.x;
                                float lf1 = u0*fe.y + u1*ff.y;
                                sigma += pf0*lf0 + pf1*lf1;
                            }
                        } else {
                            uint4 packed;
                            uint32_t* pk = &packed.x;
                            #pragma unroll
                            for (int j = 0; j < 4; j++) {
                                __half2 pf = __hmul2(hd[j], W11);
                                pf = __hfma2(hc[j], W01, pf);
                                pf = __hfma2(hb[j], W10, pf);
                                pf = __hfma2(ha[j], W00, pf);
                                __half2 lf = __hmul2(hf[j], U1);
                                lf = __hfma2(he[j], U0, lf);
                                __half2 gv = gelu_h2(__hmul2(pf, lf));
                                pk[j] = *(uint32_t*)&gv;
                            }
                            *(uint4*)(fo + pl*24 + (cc-1)*8) = packed;
                        }
                    }
                }
                if (csel == 0) out_sigma[p] = fmaxf(sigma, 0.0f);
            }
            __syncthreads();   // sole barrier per tile (double-buffered sF)

            const uint32_t a_base = a_base0 + buf * F_BUF_BYTES;

            // ================= GEMM1 =================
            float acc[8][4];
            #pragma unroll
            for (int nb = 0; nb < 8; nb++) {
                float bv0 = sBm[nb*8 + 2*q];
                float bv1 = sBm[nb*8 + 2*q + 1];
                acc[nb][0] = bv0; acc[nb][1] = bv1; acc[nb][2] = bv0; acc[nb][3] = bv1;
            }
            #pragma unroll 1
            for (int kb = 0; kb < 5; kb++) {
                uint32_t a0, a1, a2, a3;
                ldsm_x4(a0, a1, a2, a3, a_base + kb*32);
                const float* brow = sB1 + (kb*4 + q)*136 + g*2;
                #pragma unroll
                for (int nb = 0; nb < 8; nb++) {
                    uint2 bv = *(const uint2*)(brow + nb*16);
                    mma_f16(acc[nb], a0, a1, a2, a3, bv.x, bv.y);
                }
            }
            __syncwarp();
            #pragma unroll
            for (int nb = 0; nb < 8; nb++) {
                int c0 = nb*8 + 2*q;
                __half2* dA = (__half2*)(sF + (m0 + g)*F_PITCH + c0);
                __half2* dB = (__half2*)(sF + (m0 + g + 8)*F_PITCH + c0);
                *dA = gelu_h2(__floats2half2_rn(acc[nb][0], acc[nb][1]));
                *dB = gelu_h2(__floats2half2_rn(acc[nb][2], acc[nb][3]));
            }
            __syncwarp();
            // ================= GEMM2 =================
            float acc2[8][4];
            #pragma unroll
            for (int nb = 0; nb < 8; nb++)
                acc2[nb][0] = acc2[nb][1] = acc2[nb][2] = acc2[nb][3] = 0.0f;
            #pragma unroll 1
            for (int kb = 0; kb < 4; kb++) {
                uint32_t a0, a1, a2, a3;
                ldsm_x4(a0, a1, a2, a3, a_base + kb*32);
                const float* brow = sB2 + (kb*4 + q)*136 + g*2;
                #pragma unroll
                for (int nb = 0; nb < 8; nb++) {
                    uint2 bv = *(const uint2*)(brow + nb*16);
                    mma_f16(acc2[nb], a0, a1, a2, a3, bv.x, bv.y);
                }
            }
            // ---- epilogue 2 ----
            const int pA = pbase + m0 + g;
            const int pB = pA + 8;
            const float* biasA = sBiasB + (pA / NS - ray0) * 64;
            const float* biasB = sBiasB + (pB / NS - ray0) * 64;
            float rA0 = 0.f, rA1 = 0.f, rA2 = 0.f, rB0 = 0.f, rB1 = 0.f, rB2 = 0.f;
            #pragma unroll
            for (int nb = 0; nb < 8; nb++) {
                int c0 = nb*8 + 2*q, c1 = c0 + 1;
                float v00 = gelu_fast(acc2[nb][0] + biasA[c0]);
                float v01 = gelu_fast(acc2[nb][1] + biasA[c1]);
                float v10 = gelu_fast(acc2[nb][2] + biasB[c0]);
                float v11 = gelu_fast(acc2[nb][3] + biasB[c1]);
                float w00 = sW2[c0*3+0], w01 = sW2[c0*3+1], w02 = sW2[c0*3+2];
                float w10 = sW2[c1*3+0], w11 = sW2[c1*3+1], w12 = sW2[c1*3+2];
                rA0 += v00*w00 + v01*w10;
                rA1 += v00*w01 + v01*w11;
                rA2 += v00*w02 + v01*w12;
                rB0 += v10*w00 + v11*w10;
                rB1 += v10*w01 + v11*w11;
                rB2 += v10*w02 + v11*w12;
            }
            #pragma unroll
            for (int off = 1; off <= 2; off <<= 1) {
                rA0 += __shfl_xor_sync(0xffffffffu, rA0, off);
                rA1 += __shfl_xor_sync(0xffffffffu, rA1, off);
                rA2 += __shfl_xor_sync(0xffffffffu, rA2, off);
                rB0 += __shfl_xor_sync(0xffffffffu, rB0, off);
                rB1 += __shfl_xor_sync(0xffffffffu, rB1, off);
                rB2 += __shfl_xor_sync(0xffffffffu, rB2, off);
            }
            if (q == 0) {
                float c0 = b2[0], c1 = b2[1], c2 = b2[2];
                float* oA = g_rgb + (size_t)pA * 3;
                oA[0] = sigmoid_fast(rA0 + c0);
                oA[1] = sigmoid_fast(rA1 + c1);
                oA[2] = sigmoid_fast(rA2 + c2);
                float* oB = g_rgb + (size_t)pB * 3;
                oB[0] = sigmoid_fast(rB0 + c0);
                oB[1] = sigmoid_fast(rB1 + c1);
                oB[2] = sigmoid_fast(rB2 + c2);
            }
            // no trailing sync within the pipeline
        }

        // ---- chunk epilogue: this block alone produced rays [chunk*8, chunk*8+8)
        __syncthreads();   // make g_rgb / out_sigma writes visible block-wide (same-SM L1)
        if (tid < 8) {
            const int r = chunk*8 + tid;
            float T = 1.0f, a0 = 0.0f, a1 = 0.0f, a2 = 0.0f, dep = 0.0f;
            const float* rp = g_rgb + (size_t)r * NS * 3;
            float* wp = out_sigma + (size_t)r * NS;
            #pragma unroll 1
            for (int s = 0; s < NS; s++) {
                float sg = wp[s];
                float al = 1.0f - __expf(-sg * DT);
                float wt = al * T;
                T *= (1.0f - al + 1e-10f);
                wp[s] = wt;
                dep += wt * (((float)s + 0.5f) * DT);
                a0 += wt * rp[s*3+0];
                a1 += wt * rp[s*3+1];
                a2 += wt * rp[s*3+2];
            }
            out_rgb[r*3+0] = a0;
            out_rgb[r*3+1] = a1;
            out_rgb[r*3+2] = a2;
            out_depth[r]   = dep;
        }
        // no sync needed: next chunk's sampling touches disjoint global data,
        // and its pre-GEMM __syncthreads realigns the block.
    }
}

// ---------------- launch ----------------
extern "C" void kernel_launch(void* const* d_in, const int* in_sizes, int n_in,
                              void* d_out, int out_size) {
    const float* rays_o  = (const float*)d_in[0];
    const float* rays_d  = (const float*)d_in[1];
    const float* matrixs = (const float*)d_in[2];
    const float* vectors = (const float*)d_in[3];
    const float* w_mat   = (const float*)d_in[4];
    const float* b_mat   = (const float*)d_in[5];
    const float* w1      = (const float*)d_in[6];
    const float* b1      = (const float*)d_in[7];
    const float* w2      = (const float*)d_in[8];
    const float* b2      = (const float*)d_in[9];

    float* out       = (float*)d_out;
    float* out_rgb   = out;
    float* out_depth = out + NRAYS*3;
    float* out_w     = out + NRAYS*4;

    static int nsm = 0;
    if (nsm == 0) {
        cudaDeviceProp prop;
        cudaGetDeviceProperties(&prop, 0);
        nsm = prop.multiProcessorCount;
        cudaFuncSetAttribute(k_fused, cudaFuncAttributeMaxDynamicSharedMemorySize,
                             SMEM_FLOATS * sizeof(float));
    }

    k_transpose_mat<<<(3*BATCH*RES*RES*CH + 255)/256, 256>>>(matrixs);
    k_transpose_vec<<<(3*BATCH*RES*CH + 255)/256, 256>>>(vectors);
    k_bias<<<(NRAYS + 127)/128, 128>>>(rays_d, w1, b1);
    k_fused<<<2*nsm, 256, SMEM_FLOATS * sizeof(float)>>>(rays_o, rays_d, w_mat, b_mat,
                                                          w1, w2, b2,
                                                          out_rgb, out_depth, out_w);
}

// round 15
// speedup vs baseline: 1.2991x; 1.2991x over previous
#include <cuda_runtime.h>
#include <cuda_fp16.h>
#include <math.h>
#include <stdint.h>

#define BATCH 4
#define RAYS  8192
#define NRAYS (BATCH*RAYS)          // 32768
#define NS    48
#define RES   48
#define CH    32
#define NPTS  (NRAYS*NS)            // 1572864
#define NTILES (NPTS/128)           // 12288

#define DT    0.03125f

// ---------------- device scratch ----------------
__device__ __align__(16) __half g_mat_h[3*BATCH*RES*RES*CH];
__device__ __align__(16) __half g_vec_h[3*BATCH*RES*CH];
__device__ __align__(16) float  g_rgb[(size_t)NPTS*3];
__device__ __align__(16) float  g_bias[(size_t)NRAYS*64];

__device__ __forceinline__ float tanh_apx(float x) {
    float r;
    asm("tanh.approx.f32 %0, %1;" : "=f"(r) : "f"(x));
    return r;
}

__device__ __forceinline__ float sigmoid_fast(float x) {
    return 0.5f * (1.0f + tanh_apx(0.5f * x));
}

// half2 gelu: tanh-form, HW f16x2 tanh
__device__ __forceinline__ __half2 gelu_h2(__half2 x) {
    const __half2 K2  = __float2half2_rn(0.035677408f);
    const __half2 K0  = __float2half2_rn(0.7978845608f);
    const __half2 H05 = __float2half2_rn(0.5f);
    __half2 x2 = __hmul2(x, x);
    __half2 inner = __hmul2(x, __hfma2(x2, K2, K0));
    uint32_t ti;
    asm("tanh.approx.f16x2 %0, %1;" : "=r"(ti) : "r"(*(uint32_t*)&inner));
    __half2 th = *(__half2*)&ti;
    __half2 h = __hmul2(x, H05);
    return __hfma2(h, th, h);
}

__device__ __forceinline__ void mma_f16(float d[4],
                                        uint32_t a0, uint32_t a1, uint32_t a2, uint32_t a3,
                                        uint32_t b0, uint32_t b1) {
    asm volatile("mma.sync.aligned.m16n8k16.row.col.f32.f16.f16.f32 "
                 "{%0,%1,%2,%3}, {%4,%5,%6,%7}, {%8,%9}, {%0,%1,%2,%3};"
                 : "+f"(d[0]), "+f"(d[1]), "+f"(d[2]), "+f"(d[3])
                 : "r"(a0), "r"(a1), "r"(a2), "r"(a3), "r"(b0), "r"(b1));
}

__device__ __forceinline__ void ldsm_x4(uint32_t& r0, uint32_t& r1, uint32_t& r2, uint32_t& r3,
                                        uint32_t saddr) {
    asm volatile("ldmatrix.sync.aligned.m8n8.x4.shared.b16 {%0,%1,%2,%3}, [%4];"
                 : "=r"(r0), "=r"(r1), "=r"(r2), "=r"(r3) : "r"(saddr));
}

__device__ __forceinline__ uint32_t pack_h2(float lo, float hi) {
    __half2 h = __floats2half2_rn(lo, hi);
    return *(uint32_t*)&h;
}

// ---------------- prep: transposes to channel-last fp16 ----------------
__global__ void k_transpose_mat(const float* __restrict__ m) {
    int idx = blockIdx.x * blockDim.x + threadIdx.x;
    if (idx >= 3*BATCH*RES*RES*CH) return;
    int c   = idx % CH;
    int pix = (idx / CH) % (RES*RES);
    int ib  = idx / (CH*RES*RES);
    g_mat_h[idx] = __float2half_rn(m[((size_t)ib*CH + c)*(RES*RES) + pix]);
}

__global__ void k_transpose_vec(const float* __restrict__ v) {
    int idx = blockIdx.x * blockDim.x + threadIdx.x;
    if (idx >= 3*BATCH*RES*CH) return;
    int c  = idx % CH;
    int r  = (idx / CH) % RES;
    int ib = idx / (CH*RES);
    g_vec_h[idx] = __float2half_rn(v[((size_t)ib*CH + c)*RES + r]);
}

__global__ void k_bias(const float* __restrict__ rays_d,
                       const float* __restrict__ w1, const float* __restrict__ b1) {
    int q = blockIdx.x * blockDim.x + threadIdx.x;
    if (q >= NRAYS) return;
    float dx = rays_d[q*3+0], dy = rays_d[q*3+1], dz = rays_d[q*3+2];
    float inv = 1.0f / sqrtf(dx*dx + dy*dy + dz*dz);
    dx *= inv; dy *= inv; dz *= inv;
    float pe[27];
    pe[0] = dx; pe[1] = dy; pe[2] = dz;
    float f = 1.0f;
    #pragma unroll
    for (int fi = 0; fi < 4; fi++) {
        float s, c;
        sincosf(dx*f, &s, &c); pe[3 + fi*3 + 0] = s; pe[15 + fi*3 + 0] = c;
        sincosf(dy*f, &s, &c); pe[3 + fi*3 + 1] = s; pe[15 + fi*3 + 1] = c;
        sincosf(dz*f, &s, &c); pe[3 + fi*3 + 2] = s; pe[15 + fi*3 + 2] = c;
        f *= 2.0f;
    }
    float acc[64];
    #pragma unroll
    for (int j = 0; j < 64; j++) acc[j] = b1[j];
    #pragma unroll 1
    for (int k = 0; k < 27; k++) {
        float v = pe[k];
        const float* wr = w1 + (64 + k) * 64;
        #pragma unroll
        for (int j = 0; j < 64; j++) acc[j] += v * wr[j];
    }
    float* o = g_bias + (size_t)q * 64;
    #pragma unroll
    for (int j = 0; j < 64; j++) o[j] = acc[j];
}

// ---------------- fused persistent, double-buffered ----------------
#define F_PITCH 88
#define F_BUF_FLOATS (128*F_PITCH/2)      // 5632
#define F_BUF_BYTES  (F_BUF_FLOATS*4)     // 22528
#define OF_B1   (2*F_BUF_FLOATS)          // 11264
#define OF_B2   (OF_B1 + 5*4*136)         // +2720 -> 13984
#define OF_W2   (OF_B2 + 4*4*136)         // +2176 -> 16160
#define OF_BM   (OF_W2 + 192)             // 16352
#define OF_BIAS (OF_BM + 64)              // 16416, 2 x 256 floats
#define SMEM_FLOATS (OF_BIAS + 512)       // 16928 floats = 67712 B

__global__ __launch_bounds__(256, 2)
void k_fused(const float* __restrict__ rays_o, const float* __restrict__ rays_d,
             const float* __restrict__ w_mat, const float* __restrict__ b_mat,
             const float* __restrict__ w1, const float* __restrict__ w2,
             const float* __restrict__ b2, float* __restrict__ out_sigma) {
    extern __shared__ float sm[];
    float* sB1   = sm + OF_B1;
    float* sB2   = sm + OF_B2;
    float* sW2   = sm + OF_W2;
    float* sBm   = sm + OF_BM;
    float* sBias = sm + OF_BIAS;

    const int tid  = threadIdx.x;
    const int lane = tid & 31;
    const int wid  = tid >> 5;
    const int q    = lane & 3;
    const int g    = lane >> 2;

    // zero pad cols 72..79 of BOTH F buffers (never written again)
    {
        int bufr = tid >> 7, row = tid & 127;
        *(uint4*)((__half*)sm + bufr*F_BUF_FLOATS*2 + row*F_PITCH + 72) = make_uint4(0,0,0,0);
    }

    // ---- one-time fp16 weight packing (hi only) ----
    for (int i = tid; i < 5*4*64; i += 256) {
        int kb = i >> 8, qq = (i >> 6) & 3, n = i & 63;
        int k0 = kb*16 + 2*qq;
        float v0 = w_mat[k0*64 + n];
        float v1 = w_mat[(k0+1)*64 + n];
        float v2 = (k0+8 < 72) ? w_mat[(k0+8)*64 + n] : 0.0f;
        float v3 = (k0+9 < 72) ? w_mat[(k0+9)*64 + n] : 0.0f;
        uint2 e;
        e.x = pack_h2(v0, v1);
        e.y = pack_h2(v2, v3);
        *(uint2*)(sB1 + (kb*4 + qq)*136 + n*2) = e;
    }
    for (int i = tid; i < 4*4*64; i += 256) {
        int kb = i >> 8, qq = (i >> 6) & 3, n = i & 63;
        int k0 = kb*16 + 2*qq;
        uint2 e;
        e.x = pack_h2(w1[k0*64 + n],     w1[(k0+1)*64 + n]);
        e.y = pack_h2(w1[(k0+8)*64 + n], w1[(k0+9)*64 + n]);
        *(uint2*)(sB2 + (kb*4 + qq)*136 + n*2) = e;
    }
    if (tid < 192) sW2[tid] = w2[tid];
    if (tid < 64)  sBm[tid] = b_mat[tid];
    __syncthreads();

    const int m0 = wid * 16;
    const int lp   = tid >> 1;      // local point row (0..127)
    const int csel = tid & 1;       // 0: chunks 0,1   1: chunks 2,3

    const uint32_t sF_sh0 = (uint32_t)__cvta_generic_to_shared((__half*)sm);
    const uint32_t a_base0 = sF_sh0 +
        (uint32_t)(((m0 + (lane & 15)) * F_PITCH + ((lane >> 4) * 8)) * 2);

    int buf = 0;
    #pragma unroll 1
    for (int tile = blockIdx.x; tile < NTILES; tile += gridDim.x, buf ^= 1) {
        const int pbase = tile * 128;
        __half* sF    = (__half*)sm + buf * F_BUF_FLOATS * 2;
        float*  sBiasB = sBias + buf * 256;
        const int ray0 = pbase / NS;

        // ---- stage per-ray bias (<=4 rays per 128-pt tile) ----
        {
            int row = tid >> 6, col = tid & 63;
            int r = ray0 + row;
            if (r > NRAYS-1) r = NRAYS-1;
            sBiasB[row*64 + col] = g_bias[(size_t)r*64 + col];
        }

        // ================= sampling phase: 2 adjacent threads per point ========
        {
            const int p   = pbase + lp;
            const int s   = p % NS;
            const int ray = p / NS;
            const int b   = ray / RAYS;

            const float ox = rays_o[ray*3+0], oy = rays_o[ray*3+1], oz = rays_o[ray*3+2];
            const float dx = rays_d[ray*3+0], dy = rays_d[ray*3+1], dz = rays_d[ray*3+2];
            const float t  = ((float)s + 0.5f) * DT;

            const float px = ((ox + dx*t) + 0.8f) * 1.25f - 1.0f;
            const float py = ((oy + dy*t) + 0.8f) * 1.25f - 1.0f;
            const float pz = ((oz + dz*t) + 0.8f) * 1.25f - 1.0f;

            float sigma = 0.0f;
            __half* fo = sF + lp*F_PITCH;
            const int cc0 = csel*2;

            #pragma unroll 1
            for (int pl = 0; pl < 3; pl++) {
                const float cx = (pl == 0) ? px : ((pl == 1) ? pz : py);
                const float cy = (pl == 0) ? py : ((pl == 1) ? px : pz);
                const float cz = (pl == 0) ? pz : ((pl == 1) ? py : px);

                const float fx = (cx + 1.0f) * 23.5f;
                const float fy = (cy + 1.0f) * 23.5f;
                const float fz = (cz + 1.0f) * 23.5f;
                const float x0f = floorf(fx), y0f = floorf(fy), z0f = floorf(fz);
                const float wx = fx - x0f, wy = fy - y0f, wz = fz - z0f;
                const int ix0 = (int)x0f, iy0 = (int)y0f, iz0 = (int)z0f;

                const float mx0 = (ix0 >= 0  && ix0 <  RES)   ? 1.0f : 0.0f;
                const float mx1 = (ix0 >= -1 && ix0 <  RES-1) ? 1.0f : 0.0f;
                const float my0 = (iy0 >= 0  && iy0 <  RES)   ? 1.0f : 0.0f;
                const float my1 = (iy0 >= -1 && iy0 <  RES-1) ? 1.0f : 0.0f;
                const float mz0 = (iz0 >= 0  && iz0 <  RES)   ? 1.0f : 0.0f;
                const float mz1 = (iz0 >= -1 && iz0 <  RES-1) ? 1.0f : 0.0f;

                const int cx0 = min(max(ix0,   0), RES-1), cx1 = min(max(ix0+1, 0), RES-1);
                const int cy0 = min(max(iy0,   0), RES-1), cy1 = min(max(iy0+1, 0), RES-1);
                const int cz0 = min(max(iz0,   0), RES-1), cz1 = min(max(iz0+1, 0), RES-1);

                const float w00 = (1.0f-wx)*(1.0f-wy)*mx0*my0;
                const float w10 = wx*(1.0f-wy)*mx1*my0;
                const float w01 = (1.0f-wx)*wy*mx0*my1;
                const float w11 = wx*wy*mx1*my1;
                const float u0  = (1.0f-wz)*mz0;
                const float u1  = wz*mz1;

                const __half* mb = g_mat_h + ((size_t)(pl*BATCH + b) * (RES*RES)) * CH;
                const __half* vb = g_vec_h + ((size_t)(pl*BATCH + b) * RES) * CH;
                const uint4* p00 = (const uint4*)(mb + (size_t)(cy0*RES + cx0) * CH);
                const uint4* p10 = (const uint4*)(mb + (size_t)(cy0*RES + cx1) * CH);
                const uint4* p01 = (const uint4*)(mb + (size_t)(cy1*RES + cx0) * CH);
                const uint4* p11 = (const uint4*)(mb + (size_t)(cy1*RES + cx1) * CH);
                const uint4* q0  = (const uint4*)(vb + (size_t)cz0 * CH);
                const uint4* q1  = (const uint4*)(vb + (size_t)cz1 * CH);

                const __half2 W00 = __float2half2_rn(w00);
                const __half2 W10 = __float2half2_rn(w10);
                const __half2 W01 = __float2half2_rn(w01);
                const __half2 W11 = __float2half2_rn(w11);
                const __half2 U0  = __float2half2_rn(u0);
                const __half2 U1  = __float2half2_rn(u1);

                #pragma unroll
                for (int ci = 0; ci < 2; ci++) {
                    const int cc = cc0 + ci;
                    uint4 ua = p00[cc], ub = p10[cc], uc = p01[cc], ud = p11[cc];
                    uint4 ue = q0[cc],  uf = q1[cc];
                    const __half2* ha = (const __half2*)&ua;
                    const __half2* hb = (const __half2*)&ub;
                    const __half2* hc = (const __half2*)&uc;
                    const __half2* hd = (const __half2*)&ud;
                    const __half2* he = (const __half2*)&ue;
                    const __half2* hf = (const __half2*)&uf;
                    if (cc == 0) {
                        // sigma channels in fp32 (accuracy for weights output)
                        #pragma unroll
                        for (int j = 0; j < 4; j++) {
                            float2 fa = __half22float2(ha[j]);
                            float2 fb = __half22float2(hb[j]);
                            float2 fc = __half22float2(hc[j]);
                            float2 fd = __half22float2(hd[j]);
                            float2 fe = __half22float2(he[j]);
                            float2 ff = __half22float2(hf[j]);
                            float pf0 = w00*fa.x + w10*fb.x + w01*fc.x + w11*fd.x;
                            float pf1 = w00*fa.y + w10*fb.y + w01*fc.y + w11*fd.y;
                            float lf0 = u0*fe.x + u1*ff.x;
                            float lf1 = u0*fe.y + u1*ff.y;
                            sigma += pf0*lf0 + pf1*lf1;
                        }
                    } else {
                        // rgb feature channels: half2 interpolation + half2 gelu
                        uint4 packed;
                        uint32_t* pk = &packed.x;
                        #pragma unroll
                        for (int j = 0; j < 4; j++) {
                            __half2 pf = __hmul2(hd[j], W11);
                            pf = __hfma2(hc[j], W01, pf);
                            pf = __hfma2(hb[j], W10, pf);
                            pf = __hfma2(ha[j], W00, pf);
                            __half2 lf = __hmul2(hf[j], U1);
                            lf = __hfma2(he[j], U0, lf);
                            __half2 gv = gelu_h2(__hmul2(pf, lf));
                            pk[j] = *(uint32_t*)&gv;
                        }
                        *(uint4*)(fo + pl*24 + (cc-1)*8) = packed;
                    }
                }
            }
            if (csel == 0) out_sigma[p] = fmaxf(sigma, 0.0f);
        }
        __syncthreads();   // sole barrier per tile (double-buffered sF)

        const uint32_t a_base = a_base0 + buf * F_BUF_BYTES;

        // ================= GEMM1: acc = F @ Wmat + b_mat =================
        float acc[8][4];
        #pragma unroll
        for (int nb = 0; nb < 8; nb++) {
            float bv0 = sBm[nb*8 + 2*q];
            float bv1 = sBm[nb*8 + 2*q + 1];
            acc[nb][0] = bv0; acc[nb][1] = bv1; acc[nb][2] = bv0; acc[nb][3] = bv1;
        }
        #pragma unroll 1
        for (int kb = 0; kb < 5; kb++) {
            uint32_t a0, a1, a2, a3;
            ldsm_x4(a0, a1, a2, a3, a_base + kb*32);
            const float* brow = sB1 + (kb*4 + q)*136 + g*2;
            #pragma unroll
            for (int nb = 0; nb < 8; nb++) {
                uint2 bv = *(const uint2*)(brow + nb*16);
                mma_f16(acc[nb], a0, a1, a2, a3, bv.x, bv.y);
            }
        }
        __syncwarp();
        #pragma unroll
        for (int nb = 0; nb < 8; nb++) {
            int c0 = nb*8 + 2*q;
            __half2* dA = (__half2*)(sF + (m0 + g)*F_PITCH + c0);
            __half2* dB = (__half2*)(sF + (m0 + g + 8)*F_PITCH + c0);
            *dA = gelu_h2(__floats2half2_rn(acc[nb][0], acc[nb][1]));
            *dB = gelu_h2(__floats2half2_rn(acc[nb][2], acc[nb][3]));
        }
        __syncwarp();
        // ================= GEMM2: acc2 = H @ W1a =================
        float acc2[8][4];
        #pragma unroll
        for (int nb = 0; nb < 8; nb++)
            acc2[nb][0] = acc2[nb][1] = acc2[nb][2] = acc2[nb][3] = 0.0f;
        #pragma unroll 1
        for (int kb = 0; kb < 4; kb++) {
            uint32_t a0, a1, a2, a3;
            ldsm_x4(a0, a1, a2, a3, a_base + kb*32);
            const float* brow = sB2 + (kb*4 + q)*136 + g*2;
            #pragma unroll
            for (int nb = 0; nb < 8; nb++) {
                uint2 bv = *(const uint2*)(brow + nb*16);
                mma_f16(acc2[nb], a0, a1, a2, a3, bv.x, bv.y);
            }
        }
        // ---- epilogue 2: +rayBias(smem), half2 gelu, xW2 (fp32), reduce, sigmoid
        const int pA = pbase + m0 + g;
        const int pB = pA + 8;
        const float* biasA = sBiasB + (pA / NS - ray0) * 64;
        const float* biasB = sBiasB + (pB / NS - ray0) * 64;
        float rA0 = 0.f, rA1 = 0.f, rA2 = 0.f, rB0 = 0.f, rB1 = 0.f, rB2 = 0.f;
        #pragma unroll
        for (int nb = 0; nb < 8; nb++) {
            int c0 = nb*8 + 2*q, c1 = c0 + 1;
            __half2 gA = gelu_h2(__floats2half2_rn(acc2[nb][0] + biasA[c0],
                                                   acc2[nb][1] + biasA[c1]));
            __half2 gB = gelu_h2(__floats2half2_rn(acc2[nb][2] + biasB[c0],
                                                   acc2[nb][3] + biasB[c1]));
            float2 vA = __half22float2(gA);
            float2 vB = __half22float2(gB);
            float w00 = sW2[c0*3+0], w01 = sW2[c0*3+1], w02 = sW2[c0*3+2];
            float w10 = sW2[c1*3+0], w11 = sW2[c1*3+1], w12 = sW2[c1*3+2];
            rA0 += vA.x*w00 + vA.y*w10;
            rA1 += vA.x*w01 + vA.y*w11;
            rA2 += vA.x*w02 + vA.y*w12;
            rB0 += vB.x*w00 + vB.y*w10;
            rB1 += vB.x*w01 + vB.y*w11;
            rB2 += vB.x*w02 + vB.y*w12;
        }
        #pragma unroll
        for (int off = 1; off <= 2; off <<= 1) {
            rA0 += __shfl_xor_sync(0xffffffffu, rA0, off);
            rA1 += __shfl_xor_sync(0xffffffffu, rA1, off);
            rA2 += __shfl_xor_sync(0xffffffffu, rA2, off);
            rB0 += __shfl_xor_sync(0xffffffffu, rB0, off);
            rB1 += __shfl_xor_sync(0xffffffffu, rB1, off);
            rB2 += __shfl_xor_sync(0xffffffffu, rB2, off);
        }
        if (q == 0) {
            float c0 = b2[0], c1 = b2[1], c2 = b2[2];
            float* oA = g_rgb + (size_t)pA * 3;
            oA[0] = sigmoid_fast(rA0 + c0);
            oA[1] = sigmoid_fast(rA1 + c1);
            oA[2] = sigmoid_fast(rA2 + c2);
            float* oB = g_rgb + (size_t)pB * 3;
            oB[0] = sigmoid_fast(rB0 + c0);
            oB[1] = sigmoid_fast(rB1 + c1);
            oB[2] = sigmoid_fast(rB2 + c2);
        }
        // no trailing sync: next tile samples into the other buffer
    }
}

// ---------------- per-ray compositing ----------------
__global__ void k_render(float* __restrict__ out_rgb, float* __restrict__ out_depth,
                         float* __restrict__ w) {
    int qq = blockIdx.x * blockDim.x + threadIdx.x;
    if (qq >= NRAYS) return;
    float T = 1.0f, a0 = 0.0f, a1 = 0.0f, a2 = 0.0f, dep = 0.0f;
    const float* rp = g_rgb + (size_t)qq * NS * 3;
    float* wp = w + (size_t)qq * NS;
    #pragma unroll 1
    for (int s = 0; s < NS; s++) {
        float sg = wp[s];
        float al = 1.0f - __expf(-sg * DT);
        float wt = al * T;
        T *= (1.0f - al + 1e-10f);
        wp[s] = wt;
        dep += wt * (((float)s + 0.5f) * DT);
        a0 += wt * rp[s*3+0];
        a1 += wt * rp[s*3+1];
        a2 += wt * rp[s*3+2];
    }
    out_rgb[qq*3+0] = a0;
    out_rgb[qq*3+1] = a1;
    out_rgb[qq*3+2] = a2;
    out_depth[qq]   = dep;
}

// ---------------- launch ----------------
extern "C" void kernel_launch(void* const* d_in, const int* in_sizes, int n_in,
                              void* d_out, int out_size) {
    const float* rays_o  = (const float*)d_in[0];
    const float* rays_d  = (const float*)d_in[1];
    const float* matrixs = (const float*)d_in[2];
    const float* vectors = (const float*)d_in[3];
    const float* w_mat   = (const float*)d_in[4];
    const float* b_mat   = (const float*)d_in[5];
    const float* w1      = (const float*)d_in[6];
    const float* b1      = (const float*)d_in[7];
    const float* w2      = (const float*)d_in[8];
    const float* b2      = (const float*)d_in[9];

    float* out       = (float*)d_out;
    float* out_rgb   = out;
    float* out_depth = out + NRAYS*3;
    float* out_w     = out + NRAYS*4;

    static int nsm = 0;
    if (nsm == 0) {
        cudaDeviceProp prop;
        cudaGetDeviceProperties(&prop, 0);
        nsm = prop.multiProcessorCount;
        cudaFuncSetAttribute(k_fused, cudaFuncAttributeMaxDynamicSharedMemorySize,
                             SMEM_FLOATS * sizeof(float));
    }

    k_transpose_mat<<<(3*BATCH*RES*RES*CH + 255)/256, 256>>>(matrixs);
    k_transpose_vec<<<(3*BATCH*RES*CH + 255)/256, 256>>>(vectors);
    k_bias<<<(NRAYS + 127)/128, 128>>>(rays_d, w1, b1);
    k_fused<<<2*nsm, 256, SMEM_FLOATS * sizeof(float)>>>(rays_o, rays_d, w_mat, b_mat,
                                                          w1, w2, b2, out_w);
    k_render<<<(NRAYS + 127)/128, 128>>>(out_rgb, out_depth, out_w);
}

// round 16
// speedup vs baseline: 1.3703x; 1.0548x over previous
#include <cuda_runtime.h>
#include <cuda_fp16.h>
#include <math.h>
#include <stdint.h>

#define BATCH 4
#define RAYS  8192
#define NRAYS (BATCH*RAYS)          // 32768
#define NS    48
#define RES   48
#define CH    32
#define NPTS  (NRAYS*NS)            // 1572864
#define NTILES (NPTS/128)           // 12288

#define DT    0.03125f

// ---------------- device scratch ----------------
__device__ __align__(16) __half g_mat_h[3*BATCH*RES*RES*CH];
__device__ __align__(16) __half g_vec_h[3*BATCH*RES*CH];
__device__ __align__(16) float  g_rgb[(size_t)NPTS*3];
__device__ __align__(16) float  g_bias[(size_t)NRAYS*64];

__device__ __forceinline__ float tanh_apx(float x) {
    float r;
    asm("tanh.approx.f32 %0, %1;" : "=f"(r) : "f"(x));
    return r;
}

__device__ __forceinline__ float sigmoid_fast(float x) {
    return 0.5f * (1.0f + tanh_apx(0.5f * x));
}

// half2 gelu: tanh-form, HW f16x2 tanh
__device__ __forceinline__ __half2 gelu_h2(__half2 x) {
    const __half2 K2  = __float2half2_rn(0.035677408f);
    const __half2 K0  = __float2half2_rn(0.7978845608f);
    const __half2 H05 = __float2half2_rn(0.5f);
    __half2 x2 = __hmul2(x, x);
    __half2 inner = __hmul2(x, __hfma2(x2, K2, K0));
    uint32_t ti;
    asm("tanh.approx.f16x2 %0, %1;" : "=r"(ti) : "r"(*(uint32_t*)&inner));
    __half2 th = *(__half2*)&ti;
    __half2 h = __hmul2(x, H05);
    return __hfma2(h, th, h);
}

__device__ __forceinline__ void mma_f16(float d[4],
                                        uint32_t a0, uint32_t a1, uint32_t a2, uint32_t a3,
                                        uint32_t b0, uint32_t b1) {
    asm volatile("mma.sync.aligned.m16n8k16.row.col.f32.f16.f16.f32 "
                 "{%0,%1,%2,%3}, {%4,%5,%6,%7}, {%8,%9}, {%0,%1,%2,%3};"
                 : "+f"(d[0]), "+f"(d[1]), "+f"(d[2]), "+f"(d[3])
                 : "r"(a0), "r"(a1), "r"(a2), "r"(a3), "r"(b0), "r"(b1));
}

__device__ __forceinline__ void ldsm_x4(uint32_t& r0, uint32_t& r1, uint32_t& r2, uint32_t& r3,
                                        uint32_t saddr) {
    asm volatile("ldmatrix.sync.aligned.m8n8.x4.shared.b16 {%0,%1,%2,%3}, [%4];"
                 : "=r"(r0), "=r"(r1), "=r"(r2), "=r"(r3) : "r"(saddr));
}

__device__ __forceinline__ uint32_t pack_h2(float lo, float hi) {
    __half2 h = __floats2half2_rn(lo, hi);
    return *(uint32_t*)&h;
}

// ---------------- prep: transposes to channel-last fp16 ----------------
__global__ void k_transpose_mat(const float* __restrict__ m) {
    int idx = blockIdx.x * blockDim.x + threadIdx.x;
    if (idx >= 3*BATCH*RES*RES*CH) return;
    int c   = idx % CH;
    int pix = (idx / CH) % (RES*RES);
    int ib  = idx / (CH*RES*RES);
    g_mat_h[idx] = __float2half_rn(m[((size_t)ib*CH + c)*(RES*RES) + pix]);
}

__global__ void k_transpose_vec(const float* __restrict__ v) {
    int idx = blockIdx.x * blockDim.x + threadIdx.x;
    if (idx >= 3*BATCH*RES*CH) return;
    int c  = idx % CH;
    int r  = (idx / CH) % RES;
    int ib = idx / (CH*RES);
    g_vec_h[idx] = __float2half_rn(v[((size_t)ib*CH + c)*RES + r]);
}

__global__ void k_bias(const float* __restrict__ rays_d,
                       const float* __restrict__ w1, const float* __restrict__ b1) {
    int q = blockIdx.x * blockDim.x + threadIdx.x;
    if (q >= NRAYS) return;
    float dx = rays_d[q*3+0], dy = rays_d[q*3+1], dz = rays_d[q*3+2];
    float inv = 1.0f / sqrtf(dx*dx + dy*dy + dz*dz);
    dx *= inv; dy *= inv; dz *= inv;
    float pe[27];
    pe[0] = dx; pe[1] = dy; pe[2] = dz;
    float f = 1.0f;
    #pragma unroll
    for (int fi = 0; fi < 4; fi++) {
        float s, c;
        sincosf(dx*f, &s, &c); pe[3 + fi*3 + 0] = s; pe[15 + fi*3 + 0] = c;
        sincosf(dy*f, &s, &c); pe[3 + fi*3 + 1] = s; pe[15 + fi*3 + 1] = c;
        sincosf(dz*f, &s, &c); pe[3 + fi*3 + 2] = s; pe[15 + fi*3 + 2] = c;
        f *= 2.0f;
    }
    float acc[64];
    #pragma unroll
    for (int j = 0; j < 64; j++) acc[j] = b1[j];
    #pragma unroll 1
    for (int k = 0; k < 27; k++) {
        float v = pe[k];
        const float* wr = w1 + (64 + k) * 64;
        #pragma unroll
        for (int j = 0; j < 64; j++) acc[j] += v * wr[j];
    }
    float* o = g_bias + (size_t)q * 64;
    #pragma unroll
    for (int j = 0; j < 64; j++) o[j] = acc[j];
}

// ---------------- fused persistent, double-buffered ----------------
#define F_PITCH 88
#define F_BUF_FLOATS (128*F_PITCH/2)      // 5632
#define F_BUF_BYTES  (F_BUF_FLOATS*4)     // 22528
#define OF_B1   (2*F_BUF_FLOATS)          // 11264
#define OF_B2   (OF_B1 + 5*4*136)         // +2720 -> 13984
#define OF_W2   (OF_B2 + 4*4*136)         // +2176 -> 16160
#define OF_BM   (OF_W2 + 192)             // 16352
#define OF_BIAS (OF_BM + 64)              // 16416, 2 x 256 floats
#define SMEM_FLOATS (OF_BIAS + 512)       // 16928 floats = 67712 B

__global__ __launch_bounds__(256, 2)
void k_fused(const float* __restrict__ rays_o, const float* __restrict__ rays_d,
             const float* __restrict__ w_mat, const float* __restrict__ b_mat,
             const float* __restrict__ w1, const float* __restrict__ w2,
             const float* __restrict__ b2, float* __restrict__ out_sigma) {
    extern __shared__ float sm[];
    float* sB1   = sm + OF_B1;
    float* sB2   = sm + OF_B2;
    float* sW2   = sm + OF_W2;
    float* sBm   = sm + OF_BM;
    float* sBias = sm + OF_BIAS;

    const int tid  = threadIdx.x;
    const int lane = tid & 31;
    const int wid  = tid >> 5;
    const int q    = lane & 3;
    const int g    = lane >> 2;

    // zero pad cols 72..79 of BOTH F buffers (never written again)
    {
        int bufr = tid >> 7, row = tid & 127;
        *(uint4*)((__half*)sm + bufr*F_BUF_FLOATS*2 + row*F_PITCH + 72) = make_uint4(0,0,0,0);
    }

    // ---- one-time fp16 weight packing (hi only) ----
    for (int i = tid; i < 5*4*64; i += 256) {
        int kb = i >> 8, qq = (i >> 6) & 3, n = i & 63;
        int k0 = kb*16 + 2*qq;
        float v0 = w_mat[k0*64 + n];
        float v1 = w_mat[(k0+1)*64 + n];
        float v2 = (k0+8 < 72) ? w_mat[(k0+8)*64 + n] : 0.0f;
        float v3 = (k0+9 < 72) ? w_mat[(k0+9)*64 + n] : 0.0f;
        uint2 e;
        e.x = pack_h2(v0, v1);
        e.y = pack_h2(v2, v3);
        *(uint2*)(sB1 + (kb*4 + qq)*136 + n*2) = e;
    }
    for (int i = tid; i < 4*4*64; i += 256) {
        int kb = i >> 8, qq = (i >> 6) & 3, n = i & 63;
        int k0 = kb*16 + 2*qq;
        uint2 e;
        e.x = pack_h2(w1[k0*64 + n],     w1[(k0+1)*64 + n]);
        e.y = pack_h2(w1[(k0+8)*64 + n], w1[(k0+9)*64 + n]);
        *(uint2*)(sB2 + (kb*4 + qq)*136 + n*2) = e;
    }
    if (tid < 192) sW2[tid] = w2[tid];
    if (tid < 64)  sBm[tid] = b_mat[tid];
    __syncthreads();

    const int m0 = wid * 16;
    const int lp   = tid >> 1;      // local point row (0..127)
    const int csel = tid & 1;       // 0: chunks 0,1   1: chunks 2,3

    const uint32_t sF_sh0 = (uint32_t)__cvta_generic_to_shared((__half*)sm);
    const uint32_t a_base0 = sF_sh0 +
        (uint32_t)(((m0 + (lane & 15)) * F_PITCH + ((lane >> 4) * 8)) * 2);

    int buf = 0;
    #pragma unroll 1
    for (int tile = blockIdx.x; tile < NTILES; tile += gridDim.x, buf ^= 1) {
        const int pbase = tile * 128;
        __half* sF    = (__half*)sm + buf * F_BUF_FLOATS * 2;
        float*  sBiasB = sBias + buf * 256;
        const int ray0 = pbase / NS;

        // ---- stage per-ray bias (<=4 rays per 128-pt tile) ----
        {
            int row = tid >> 6, col = tid & 63;
            int r = ray0 + row;
            if (r > NRAYS-1) r = NRAYS-1;
            sBiasB[row*64 + col] = g_bias[(size_t)r*64 + col];
        }

        // ================= sampling phase: 2 adjacent threads per point ========
        {
            const int p   = pbase + lp;
            const int s   = p % NS;
            const int ray = p / NS;
            const int b   = ray / RAYS;

            const float ox = rays_o[ray*3+0], oy = rays_o[ray*3+1], oz = rays_o[ray*3+2];
            const float dx = rays_d[ray*3+0], dy = rays_d[ray*3+1], dz = rays_d[ray*3+2];
            const float t  = ((float)s + 0.5f) * DT;

            // per-axis interpolation data (computed ONCE, permuted per plane)
            // grid coord: fa = ((pos+0.8)*1.25 - 1 + 1)*23.5 = pos*29.375 + 23.5
            float pos[3];
            pos[0] = ox + dx*t;
            pos[1] = oy + dy*t;
            pos[2] = oz + dz*t;
            float t0a[3], t1a[3];
            int c0a[3], c1a[3];
            #pragma unroll
            for (int a = 0; a < 3; a++) {
                float fa  = fmaf(pos[a], 29.375f, 23.5f);
                float f0  = floorf(fa);
                float w   = fa - f0;
                int   ia  = (int)f0;
                float m0_ = (ia >= 0  && ia <  RES)   ? 1.0f : 0.0f;
                float m1_ = (ia >= -1 && ia <  RES-1) ? 1.0f : 0.0f;
                t0a[a] = (1.0f - w) * m0_;
                t1a[a] = w * m1_;
                c0a[a] = min(max(ia,   0), RES-1);
                c1a[a] = min(max(ia+1, 0), RES-1);
            }

            float sigma = 0.0f;
            __half* fo = sF + lp*F_PITCH;
            const int cc0 = csel*2;

            // plane axis permutation: MAT_MODE=[[0,1],[2,0],[1,2]], VEC_MODE=[2,1,0]
            const int AXv[3] = {0, 2, 1};
            const int BXv[3] = {1, 0, 2};
            const int CXv[3] = {2, 1, 0};

            #pragma unroll
            for (int pl = 0; pl < 3; pl++) {
                const int A = AXv[pl], B = BXv[pl], C = CXv[pl];
                const float w00 = t0a[A]*t0a[B];
                const float w10 = t1a[A]*t0a[B];
                const float w01 = t0a[A]*t1a[B];
                const float w11 = t1a[A]*t1a[B];
                const float u0  = t0a[C];
                const float u1  = t1a[C];

                const __half* mb = g_mat_h + ((size_t)(pl*BATCH + b) * (RES*RES)) * CH;
                const __half* vb = g_vec_h + ((size_t)(pl*BATCH + b) * RES) * CH;
                const uint4* p00 = (const uint4*)(mb + (size_t)(c0a[B]*RES + c0a[A]) * CH);
                const uint4* p10 = (const uint4*)(mb + (size_t)(c0a[B]*RES + c1a[A]) * CH);
                const uint4* p01 = (const uint4*)(mb + (size_t)(c1a[B]*RES + c0a[A]) * CH);
                const uint4* p11 = (const uint4*)(mb + (size_t)(c1a[B]*RES + c1a[A]) * CH);
                const uint4* q0  = (const uint4*)(vb + (size_t)c0a[C] * CH);
                const uint4* q1  = (const uint4*)(vb + (size_t)c1a[C] * CH);

                const __half2 W00 = __float2half2_rn(w00);
                const __half2 W10 = __float2half2_rn(w10);
                const __half2 W01 = __float2half2_rn(w01);
                const __half2 W11 = __float2half2_rn(w11);
                const __half2 U0  = __float2half2_rn(u0);
                const __half2 U1  = __float2half2_rn(u1);

                #pragma unroll
                for (int ci = 0; ci < 2; ci++) {
                    const int cc = cc0 + ci;
                    uint4 ua = p00[cc], ub = p10[cc], uc = p01[cc], ud = p11[cc];
                    uint4 ue = q0[cc],  uf = q1[cc];
                    const __half2* ha = (const __half2*)&ua;
                    const __half2* hb = (const __half2*)&ub;
                    const __half2* hc = (const __half2*)&uc;
                    const __half2* hd = (const __half2*)&ud;
                    const __half2* he = (const __half2*)&ue;
                    const __half2* hf = (const __half2*)&uf;
                    if (cc == 0) {
                        // sigma channels in fp32 (accuracy for weights output)
                        #pragma unroll
                        for (int j = 0; j < 4; j++) {
                            float2 fa = __half22float2(ha[j]);
                            float2 fb = __half22float2(hb[j]);
                            float2 fc = __half22float2(hc[j]);
                            float2 fd = __half22float2(hd[j]);
                            float2 fe = __half22float2(he[j]);
                            float2 ff = __half22float2(hf[j]);
                            float pf0 = w00*fa.x + w10*fb.x + w01*fc.x + w11*fd.x;
                            float pf1 = w00*fa.y + w10*fb.y + w01*fc.y + w11*fd.y;
                            float lf0 = u0*fe.x + u1*ff.x;
                            float lf1 = u0*fe.y + u1*ff.y;
                            sigma += pf0*lf0 + pf1*lf1;
                        }
                    } else {
                        // rgb feature channels: half2 interpolation + half2 gelu
                        uint4 packed;
                        uint32_t* pk = &packed.x;
                        #pragma unroll
                        for (int j = 0; j < 4; j++) {
                            __half2 pf = __hmul2(hd[j], W11);
                            pf = __hfma2(hc[j], W01, pf);
                            pf = __hfma2(hb[j], W10, pf);
                            pf = __hfma2(ha[j], W00, pf);
                            __half2 lf = __hmul2(hf[j], U1);
                            lf = __hfma2(he[j], U0, lf);
                            __half2 gv = gelu_h2(__hmul2(pf, lf));
                            pk[j] = *(uint32_t*)&gv;
                        }
                        *(uint4*)(fo + pl*24 + (cc-1)*8) = packed;
                    }
                }
            }
            if (csel == 0) out_sigma[p] = fmaxf(sigma, 0.0f);
        }
        __syncthreads();   // sole barrier per tile (double-buffered sF)

        const uint32_t a_base = a_base0 + buf * F_BUF_BYTES;

        // ================= GEMM1: acc = F @ Wmat + b_mat =================
        float acc[8][4];
        #pragma unroll
        for (int nb = 0; nb < 8; nb++) {
            float bv0 = sBm[nb*8 + 2*q];
            float bv1 = sBm[nb*8 + 2*q + 1];
            acc[nb][0] = bv0; acc[nb][1] = bv1; acc[nb][2] = bv0; acc[nb][3] = bv1;
        }
        #pragma unroll 1
        for (int kb = 0; kb < 5; kb++) {
            uint32_t a0, a1, a2, a3;
            ldsm_x4(a0, a1, a2, a3, a_base + kb*32);
            const float* brow = sB1 + (kb*4 + q)*136 + g*2;
            #pragma unroll
            for (int nb = 0; nb < 8; nb++) {
                uint2 bv = *(const uint2*)(brow + nb*16);
                mma_f16(acc[nb], a0, a1, a2, a3, bv.x, bv.y);
            }
        }
        __syncwarp();
        #pragma unroll
        for (int nb = 0; nb < 8; nb++) {
            int c0 = nb*8 + 2*q;
            __half2* dA = (__half2*)(sF + (m0 + g)*F_PITCH + c0);
            __half2* dB = (__half2*)(sF + (m0 + g + 8)*F_PITCH + c0);
            *dA = gelu_h2(__floats2half2_rn(acc[nb][0], acc[nb][1]));
            *dB = gelu_h2(__floats2half2_rn(acc[nb][2], acc[nb][3]));
        }
        __syncwarp();
        // ================= GEMM2: acc2 = H @ W1a =================
        float acc2[8][4];
        #pragma unroll
        for (int nb = 0; nb < 8; nb++)
            acc2[nb][0] = acc2[nb][1] = acc2[nb][2] = acc2[nb][3] = 0.0f;
        #pragma unroll 1
        for (int kb = 0; kb < 4; kb++) {
            uint32_t a0, a1, a2, a3;
            ldsm_x4(a0, a1, a2, a3, a_base + kb*32);
            const float* brow = sB2 + (kb*4 + q)*136 + g*2;
            #pragma unroll
            for (int nb = 0; nb < 8; nb++) {
                uint2 bv = *(const uint2*)(brow + nb*16);
                mma_f16(acc2[nb], a0, a1, a2, a3, bv.x, bv.y);
            }
        }
        // ---- epilogue 2: +rayBias(smem), half2 gelu, xW2 (fp32), reduce, sigmoid
        const int pA = pbase + m0 + g;
        const int pB = pA + 8;
        const float* biasA = sBiasB + (pA / NS - ray0) * 64;
        const float* biasB = sBiasB + (pB / NS - ray0) * 64;
        float rA0 = 0.f, rA1 = 0.f, rA2 = 0.f, rB0 = 0.f, rB1 = 0.f, rB2 = 0.f;
        #pragma unroll
        for (int nb = 0; nb < 8; nb++) {
            int c0 = nb*8 + 2*q, c1 = c0 + 1;
            __half2 gA = gelu_h2(__floats2half2_rn(acc2[nb][0] + biasA[c0],
                                                   acc2[nb][1] + biasA[c1]));
            __half2 gB = gelu_h2(__floats2half2_rn(acc2[nb][2] + biasB[c0],
                                                   acc2[nb][3] + biasB[c1]));
            float2 vA = __half22float2(gA);
            float2 vB = __half22float2(gB);
            float w00 = sW2[c0*3+0], w01 = sW2[c0*3+1], w02 = sW2[c0*3+2];
            float w10 = sW2[c1*3+0], w11 = sW2[c1*3+1], w12 = sW2[c1*3+2];
            rA0 += vA.x*w00 + vA.y*w10;
            rA1 += vA.x*w01 + vA.y*w11;
            rA2 += vA.x*w02 + vA.y*w12;
            rB0 += vB.x*w00 + vB.y*w10;
            rB1 += vB.x*w01 + vB.y*w11;
            rB2 += vB.x*w02 + vB.y*w12;
        }
        #pragma unroll
        for (int off = 1; off <= 2; off <<= 1) {
            rA0 += __shfl_xor_sync(0xffffffffu, rA0, off);
            rA1 += __shfl_xor_sync(0xffffffffu, rA1, off);
            rA2 += __shfl_xor_sync(0xffffffffu, rA2, off);
            rB0 += __shfl_xor_sync(0xffffffffu, rB0, off);
            rB1 += __shfl_xor_sync(0xffffffffu, rB1, off);
            rB2 += __shfl_xor_sync(0xffffffffu, rB2, off);
        }
        if (q == 0) {
            float c0 = b2[0], c1 = b2[1], c2 = b2[2];
            float* oA = g_rgb + (size_t)pA * 3;
            oA[0] = sigmoid_fast(rA0 + c0);
            oA[1] = sigmoid_fast(rA1 + c1);
            oA[2] = sigmoid_fast(rA2 + c2);
            float* oB = g_rgb + (size_t)pB * 3;
            oB[0] = sigmoid_fast(rB0 + c0);
            oB[1] = sigmoid_fast(rB1 + c1);
            oB[2] = sigmoid_fast(rB2 + c2);
        }
        // no trailing sync: next tile samples into the other buffer
    }
}

// ---------------- per-ray compositing ----------------
__global__ void k_render(float* __restrict__ out_rgb, float* __restrict__ out_depth,
                         float* __restrict__ w) {
    int qq = blockIdx.x * blockDim.x + threadIdx.x;
    if (qq >= NRAYS) return;
    float T = 1.0f, a0 = 0.0f, a1 = 0.0f, a2 = 0.0f, dep = 0.0f;
    const float* rp = g_rgb + (size_t)qq * NS * 3;
    float* wp = w + (size_t)qq * NS;
    #pragma unroll 1
    for (int s = 0; s < NS; s++) {
        float sg = wp[s];
        float al = 1.0f - __expf(-sg * DT);
        float wt = al * T;
        T *= (1.0f - al + 1e-10f);
        wp[s] = wt;
        dep += wt * (((float)s + 0.5f) * DT);
        a0 += wt * rp[s*3+0];
        a1 += wt * rp[s*3+1];
        a2 += wt * rp[s*3+2];
    }
    out_rgb[qq*3+0] = a0;
    out_rgb[qq*3+1] = a1;
    out_rgb[qq*3+2] = a2;
    out_depth[qq]   = dep;
}

// ---------------- launch ----------------
extern "C" void kernel_launch(void* const* d_in, const int* in_sizes, int n_in,
                              void* d_out, int out_size) {
    const float* rays_o  = (const float*)d_in[0];
    const float* rays_d  = (const float*)d_in[1];
    const float* matrixs = (const float*)d_in[2];
    const float* vectors = (const float*)d_in[3];
    const float* w_mat   = (const float*)d_in[4];
    const float* b_mat   = (const float*)d_in[5];
    const float* w1      = (const float*)d_in[6];
    const float* b1      = (const float*)d_in[7];
    const float* w2      = (const float*)d_in[8];
    const float* b2      = (const float*)d_in[9];

    float* out       = (float*)d_out;
    float* out_rgb   = out;
    float* out_depth = out + NRAYS*3;
    float* out_w     = out + NRAYS*4;

    static int nsm = 0;
    if (nsm == 0) {
        cudaDeviceProp prop;
        cudaGetDeviceProperties(&prop, 0);
        nsm = prop.multiProcessorCount;
        cudaFuncSetAttribute(k_fused, cudaFuncAttributeMaxDynamicSharedMemorySize,
                             SMEM_FLOATS * sizeof(float));
    }

    k_transpose_mat<<<(3*BATCH*RES*RES*CH + 255)/256, 256>>>(matrixs);
    k_transpose_vec<<<(3*BATCH*RES*CH + 255)/256, 256>>>(vectors);
    k_bias<<<(NRAYS + 127)/128, 128>>>(rays_d, w1, b1);
    k_fused<<<2*nsm, 256, SMEM_FLOATS * sizeof(float)>>>(rays_o, rays_d, w_mat, b_mat,
                                                          w1, w2, b2, out_w);
    k_render<<<(NRAYS + 127)/128, 128>>>(out_rgb, out_depth, out_w);
}

// round 17
// speedup vs baseline: 1.4030x; 1.0239x over previous
#include <cuda_runtime.h>
#include <cuda_fp16.h>
#include <math.h>
#include <stdint.h>

#define BATCH 4
#define RAYS  8192
#define NRAYS (BATCH*RAYS)          // 32768
#define NS    48
#define RES   48
#define CH    32
#define NPTS  (NRAYS*NS)            // 1572864
#define NTILES (NPTS/128)           // 12288
#define MATN  (3*BATCH*RES*RES*CH)  // 884736
#define VECN  (3*BATCH*RES*CH)      // 18432

#define DT    0.03125f

// ---------------- device scratch (64B aligned for 256-bit loads) ----------------
__device__ __align__(64) __half g_mat_h[MATN];
__device__ __align__(64) __half g_vec_h[VECN];
__device__ __align__(16) float  g_rgb[(size_t)NPTS*3];
__device__ __align__(16) float  g_bias[(size_t)NRAYS*64];

__device__ __forceinline__ float tanh_apx(float x) {
    float r;
    asm("tanh.approx.f32 %0, %1;" : "=f"(r) : "f"(x));
    return r;
}

__device__ __forceinline__ float sigmoid_fast(float x) {
    return 0.5f * (1.0f + tanh_apx(0.5f * x));
}

// half2 gelu: tanh-form, HW f16x2 tanh
__device__ __forceinline__ __half2 gelu_h2(__half2 x) {
    const __half2 K2  = __float2half2_rn(0.035677408f);
    const __half2 K0  = __float2half2_rn(0.7978845608f);
    const __half2 H05 = __float2half2_rn(0.5f);
    __half2 x2 = __hmul2(x, x);
    __half2 inner = __hmul2(x, __hfma2(x2, K2, K0));
    uint32_t ti;
    asm("tanh.approx.f16x2 %0, %1;" : "=r"(ti) : "r"(*(uint32_t*)&inner));
    __half2 th = *(__half2*)&ti;
    __half2 h = __hmul2(x, H05);
    return __hfma2(h, th, h);
}

__device__ __forceinline__ void mma_f16(float d[4],
                                        uint32_t a0, uint32_t a1, uint32_t a2, uint32_t a3,
                                        uint32_t b0, uint32_t b1) {
    asm volatile("mma.sync.aligned.m16n8k16.row.col.f32.f16.f16.f32 "
                 "{%0,%1,%2,%3}, {%4,%5,%6,%7}, {%8,%9}, {%0,%1,%2,%3};"
                 : "+f"(d[0]), "+f"(d[1]), "+f"(d[2]), "+f"(d[3])
                 : "r"(a0), "r"(a1), "r"(a2), "r"(a3), "r"(b0), "r"(b1));
}

__device__ __forceinline__ void ldsm_x4(uint32_t& r0, uint32_t& r1, uint32_t& r2, uint32_t& r3,
                                        uint32_t saddr) {
    asm volatile("ldmatrix.sync.aligned.m8n8.x4.shared.b16 {%0,%1,%2,%3}, [%4];"
                 : "=r"(r0), "=r"(r1), "=r"(r2), "=r"(r3) : "r"(saddr));
}

// 256-bit global load (sm_100+)
__device__ __forceinline__ void ldg256(uint4& lo, uint4& hi, const void* p) {
    asm volatile("ld.global.v8.b32 {%0,%1,%2,%3,%4,%5,%6,%7}, [%8];"
                 : "=r"(lo.x), "=r"(lo.y), "=r"(lo.z), "=r"(lo.w),
                   "=r"(hi.x), "=r"(hi.y), "=r"(hi.z), "=r"(hi.w)
                 : "l"(p));
}

__device__ __forceinline__ uint32_t pack_h2(float lo, float hi) {
    __half2 h = __floats2half2_rn(lo, hi);
    return *(uint32_t*)&h;
}

// ---------------- merged prep: transposes + per-ray bias ----------------
__global__ void k_prep(const float* __restrict__ m, const float* __restrict__ v,
                       const float* __restrict__ rays_d,
                       const float* __restrict__ w1, const float* __restrict__ b1) {
    const int idx0   = blockIdx.x * blockDim.x + threadIdx.x;
    const int stride = gridDim.x * blockDim.x;

    for (int idx = idx0; idx < MATN; idx += stride) {
        int c   = idx % CH;
        int pix = (idx / CH) % (RES*RES);
        int ib  = idx / (CH*RES*RES);
        g_mat_h[idx] = __float2half_rn(m[((size_t)ib*CH + c)*(RES*RES) + pix]);
    }
    for (int idx = idx0; idx < VECN; idx += stride) {
        int c  = idx % CH;
        int r  = (idx / CH) % RES;
        int ib = idx / (CH*RES);
        g_vec_h[idx] = __float2half_rn(v[((size_t)ib*CH + c)*RES + r]);
    }
    for (int r = idx0; r < NRAYS; r += stride) {
        float dx = rays_d[r*3+0], dy = rays_d[r*3+1], dz = rays_d[r*3+2];
        float inv = 1.0f / sqrtf(dx*dx + dy*dy + dz*dz);
        dx *= inv; dy *= inv; dz *= inv;
        float pe[27];
        pe[0] = dx; pe[1] = dy; pe[2] = dz;
        float f = 1.0f;
        #pragma unroll
        for (int fi = 0; fi < 4; fi++) {
            float s, c;
            sincosf(dx*f, &s, &c); pe[3 + fi*3 + 0] = s; pe[15 + fi*3 + 0] = c;
            sincosf(dy*f, &s, &c); pe[3 + fi*3 + 1] = s; pe[15 + fi*3 + 1] = c;
            sincosf(dz*f, &s, &c); pe[3 + fi*3 + 2] = s; pe[15 + fi*3 + 2] = c;
            f *= 2.0f;
        }
        #pragma unroll 1
        for (int jb = 0; jb < 2; jb++) {
            float acc[32];
            #pragma unroll
            for (int j = 0; j < 32; j++) acc[j] = b1[jb*32 + j];
            #pragma unroll 1
            for (int k = 0; k < 27; k++) {
                float vv = pe[k];
                const float* wr = w1 + (64 + k)*64 + jb*32;
                #pragma unroll
                for (int j = 0; j < 32; j++) acc[j] += vv * wr[j];
            }
            float* o = g_bias + (size_t)r*64 + jb*32;
            #pragma unroll
            for (int j = 0; j < 32; j++) o[j] = acc[j];
        }
    }
}

// ---------------- fused persistent, double-buffered ----------------
#define F_PITCH 88
#define F_BUF_FLOATS (128*F_PITCH/2)      // 5632
#define F_BUF_BYTES  (F_BUF_FLOATS*4)     // 22528
#define OF_B1   (2*F_BUF_FLOATS)          // 11264
#define OF_B2   (OF_B1 + 5*4*136)         // +2720 -> 13984
#define OF_W2   (OF_B2 + 4*4*136)         // +2176 -> 16160
#define OF_BM   (OF_W2 + 192)             // 16352
#define OF_BIAS (OF_BM + 64)              // 16416, 2 x 256 floats
#define SMEM_FLOATS (OF_BIAS + 512)       // 16928 floats = 67712 B

__global__ __launch_bounds__(256, 2)
void k_fused(const float* __restrict__ rays_o, const float* __restrict__ rays_d,
             const float* __restrict__ w_mat, const float* __restrict__ b_mat,
             const float* __restrict__ w1, const float* __restrict__ w2,
             const float* __restrict__ b2, float* __restrict__ out_sigma) {
    extern __shared__ float sm[];
    float* sB1   = sm + OF_B1;
    float* sB2   = sm + OF_B2;
    float* sW2   = sm + OF_W2;
    float* sBm   = sm + OF_BM;
    float* sBias = sm + OF_BIAS;

    const int tid  = threadIdx.x;
    const int lane = tid & 31;
    const int wid  = tid >> 5;
    const int q    = lane & 3;
    const int g    = lane >> 2;

    // zero pad cols 72..79 of BOTH F buffers (never written again)
    {
        int bufr = tid >> 7, row = tid & 127;
        *(uint4*)((__half*)sm + bufr*F_BUF_FLOATS*2 + row*F_PITCH + 72) = make_uint4(0,0,0,0);
    }

    // ---- one-time fp16 weight packing (hi only) ----
    for (int i = tid; i < 5*4*64; i += 256) {
        int kb = i >> 8, qq = (i >> 6) & 3, n = i & 63;
        int k0 = kb*16 + 2*qq;
        float v0 = w_mat[k0*64 + n];
        float v1 = w_mat[(k0+1)*64 + n];
        float v2 = (k0+8 < 72) ? w_mat[(k0+8)*64 + n] : 0.0f;
        float v3 = (k0+9 < 72) ? w_mat[(k0+9)*64 + n] : 0.0f;
        uint2 e;
        e.x = pack_h2(v0, v1);
        e.y = pack_h2(v2, v3);
        *(uint2*)(sB1 + (kb*4 + qq)*136 + n*2) = e;
    }
    for (int i = tid; i < 4*4*64; i += 256) {
        int kb = i >> 8, qq = (i >> 6) & 3, n = i & 63;
        int k0 = kb*16 + 2*qq;
        uint2 e;
        e.x = pack_h2(w1[k0*64 + n],     w1[(k0+1)*64 + n]);
        e.y = pack_h2(w1[(k0+8)*64 + n], w1[(k0+9)*64 + n]);
        *(uint2*)(sB2 + (kb*4 + qq)*136 + n*2) = e;
    }
    if (tid < 192) sW2[tid] = w2[tid];
    if (tid < 64)  sBm[tid] = b_mat[tid];
    __syncthreads();

    const int m0 = wid * 16;
    const int lp   = tid >> 1;      // local point row (0..127)
    const int csel = tid & 1;       // 0: chunks 0,1   1: chunks 2,3

    const uint32_t sF_sh0 = (uint32_t)__cvta_generic_to_shared((__half*)sm);
    const uint32_t a_base0 = sF_sh0 +
        (uint32_t)(((m0 + (lane & 15)) * F_PITCH + ((lane >> 4) * 8)) * 2);

    int buf = 0;
    #pragma unroll 1
    for (int tile = blockIdx.x; tile < NTILES; tile += gridDim.x, buf ^= 1) {
        const int pbase = tile * 128;
        __half* sF    = (__half*)sm + buf * F_BUF_FLOATS * 2;
        float*  sBiasB = sBias + buf * 256;
        const int ray0 = pbase / NS;

        // ---- stage per-ray bias (<=4 rays per 128-pt tile) ----
        {
            int row = tid >> 6, col = tid & 63;
            int r = ray0 + row;
            if (r > NRAYS-1) r = NRAYS-1;
            sBiasB[row*64 + col] = g_bias[(size_t)r*64 + col];
        }

        // ================= sampling phase: 2 adjacent threads per point ========
        {
            const int p   = pbase + lp;
            const int s   = p % NS;
            const int ray = p / NS;
            const int b   = ray / RAYS;

            const float ox = rays_o[ray*3+0], oy = rays_o[ray*3+1], oz = rays_o[ray*3+2];
            const float dx = rays_d[ray*3+0], dy = rays_d[ray*3+1], dz = rays_d[ray*3+2];
            const float t  = ((float)s + 0.5f) * DT;

            float pos[3];
            pos[0] = ox + dx*t;
            pos[1] = oy + dy*t;
            pos[2] = oz + dz*t;
            float t0a[3], t1a[3];
            int c0a[3], c1a[3];
            #pragma unroll
            for (int a = 0; a < 3; a++) {
                float fa  = fmaf(pos[a], 29.375f, 23.5f);
                float f0  = floorf(fa);
                float w   = fa - f0;
                int   ia  = (int)f0;
                float m0_ = (ia >= 0  && ia <  RES)   ? 1.0f : 0.0f;
                float m1_ = (ia >= -1 && ia <  RES-1) ? 1.0f : 0.0f;
                t0a[a] = (1.0f - w) * m0_;
                t1a[a] = w * m1_;
                c0a[a] = min(max(ia,   0), RES-1);
                c1a[a] = min(max(ia+1, 0), RES-1);
            }

            float sigma = 0.0f;
            __half* fo = sF + lp*F_PITCH;
            const int off16 = csel * 2;       // uint4-chunk offset of this thread's 32B half

            const int AXv[3] = {0, 2, 1};
            const int BXv[3] = {1, 0, 2};
            const int CXv[3] = {2, 1, 0};

            #pragma unroll
            for (int pl = 0; pl < 3; pl++) {
                const int A = AXv[pl], B = BXv[pl], C = CXv[pl];
                const float w00 = t0a[A]*t0a[B];
                const float w10 = t1a[A]*t0a[B];
                const float w01 = t0a[A]*t1a[B];
                const float w11 = t1a[A]*t1a[B];
                const float u0  = t0a[C];
                const float u1  = t1a[C];

                const __half* mb = g_mat_h + ((size_t)(pl*BATCH + b) * (RES*RES)) * CH;
                const __half* vb = g_vec_h + ((size_t)(pl*BATCH + b) * RES) * CH;
                const uint4* p00 = (const uint4*)(mb + (size_t)(c0a[B]*RES + c0a[A]) * CH) + off16;
                const uint4* p10 = (const uint4*)(mb + (size_t)(c0a[B]*RES + c1a[A]) * CH) + off16;
                const uint4* p01 = (const uint4*)(mb + (size_t)(c1a[B]*RES + c0a[A]) * CH) + off16;
                const uint4* p11 = (const uint4*)(mb + (size_t)(c1a[B]*RES + c1a[A]) * CH) + off16;
                const uint4* q0  = (const uint4*)(vb + (size_t)c0a[C] * CH) + off16;
                const uint4* q1  = (const uint4*)(vb + (size_t)c1a[C] * CH) + off16;

                const __half2 W00 = __float2half2_rn(w00);
                const __half2 W10 = __float2half2_rn(w10);
                const __half2 W01 = __float2half2_rn(w01);
                const __half2 W11 = __float2half2_rn(w11);
                const __half2 U0  = __float2half2_rn(u0);
                const __half2 U1  = __float2half2_rn(u1);

                // 256-bit loads: both 16B chunks of this thread's half per tap
                uint4 a0c, a1c, b0c, b1c, c0c, c1c, d0c, d1c, e0c, e1c, f0c, f1c;
                ldg256(a0c, a1c, p00);
                ldg256(b0c, b1c, p10);
                ldg256(c0c, c1c, p01);
                ldg256(d0c, d1c, p11);
                ldg256(e0c, e1c, q0);
                ldg256(f0c, f1c, q1);

                #pragma unroll
                for (int ci = 0; ci < 2; ci++) {
                    const int cc = off16 + ci;
                    uint4 ua = ci ? a1c : a0c;
                    uint4 ub = ci ? b1c : b0c;
                    uint4 uc = ci ? c1c : c0c;
                    uint4 ud = ci ? d1c : d0c;
                    uint4 ue = ci ? e1c : e0c;
                    uint4 uf = ci ? f1c : f0c;
                    const __half2* ha = (const __half2*)&ua;
                    const __half2* hb = (const __half2*)&ub;
                    const __half2* hc = (const __half2*)&uc;
                    const __half2* hd = (const __half2*)&ud;
                    const __half2* he = (const __half2*)&ue;
                    const __half2* hf = (const __half2*)&uf;
                    if (cc == 0) {
                        // sigma channels in fp32 (accuracy for weights output)
                        #pragma unroll
                        for (int j = 0; j < 4; j++) {
                            float2 fa = __half22float2(ha[j]);
                            float2 fb = __half22float2(hb[j]);
                            float2 fc = __half22float2(hc[j]);
                            float2 fd = __half22float2(hd[j]);
                            float2 fe = __half22float2(he[j]);
                            float2 ff = __half22float2(hf[j]);
                            float pf0 = w00*fa.x + w10*fb.x + w01*fc.x + w11*fd.x;
                            float pf1 = w00*fa.y + w10*fb.y + w01*fc.y + w11*fd.y;
                            float lf0 = u0*fe.x + u1*ff.x;
                            float lf1 = u0*fe.y + u1*ff.y;
                            sigma += pf0*lf0 + pf1*lf1;
                        }
                    } else {
                        // rgb feature channels: half2 interpolation + half2 gelu
                        uint4 packed;
                        uint32_t* pk = &packed.x;
                        #pragma unroll
                        for (int j = 0; j < 4; j++) {
                            __half2 pf = __hmul2(hd[j], W11);
                            pf = __hfma2(hc[j], W01, pf);
                            pf = __hfma2(hb[j], W10, pf);
                            pf = __hfma2(ha[j], W00, pf);
                            __half2 lf = __hmul2(hf[j], U1);
                            lf = __hfma2(he[j], U0, lf);
                            __half2 gv = gelu_h2(__hmul2(pf, lf));
                            pk[j] = *(uint32_t*)&gv;
                        }
                        *(uint4*)(fo + pl*24 + (cc-1)*8) = packed;
                    }
                }
            }
            if (csel == 0) out_sigma[p] = fmaxf(sigma, 0.0f);
        }
        __syncthreads();   // sole barrier per tile (double-buffered sF)

        const uint32_t a_base = a_base0 + buf * F_BUF_BYTES;

        // ================= GEMM1: acc = F @ Wmat + b_mat =================
        float acc[8][4];
        #pragma unroll
        for (int nb = 0; nb < 8; nb++) {
            float bv0 = sBm[nb*8 + 2*q];
            float bv1 = sBm[nb*8 + 2*q + 1];
            acc[nb][0] = bv0; acc[nb][1] = bv1; acc[nb][2] = bv0; acc[nb][3] = bv1;
        }
        #pragma unroll 1
        for (int kb = 0; kb < 5; kb++) {
            uint32_t a0, a1, a2, a3;
            ldsm_x4(a0, a1, a2, a3, a_base + kb*32);
            const float* brow = sB1 + (kb*4 + q)*136 + g*2;
            #pragma unroll
            for (int nb = 0; nb < 8; nb++) {
                uint2 bv = *(const uint2*)(brow + nb*16);
                mma_f16(acc[nb], a0, a1, a2, a3, bv.x, bv.y);
            }
        }
        __syncwarp();
        #pragma unroll
        for (int nb = 0; nb < 8; nb++) {
            int c0 = nb*8 + 2*q;
            __half2* dA = (__half2*)(sF + (m0 + g)*F_PITCH + c0);
            __half2* dB = (__half2*)(sF + (m0 + g + 8)*F_PITCH + c0);
            *dA = gelu_h2(__floats2half2_rn(acc[nb][0], acc[nb][1]));
            *dB = gelu_h2(__floats2half2_rn(acc[nb][2], acc[nb][3]));
        }
        __syncwarp();
        // ================= GEMM2: acc2 = H @ W1a =================
        float acc2[8][4];
        #pragma unroll
        for (int nb = 0; nb < 8; nb++)
            acc2[nb][0] = acc2[nb][1] = acc2[nb][2] = acc2[nb][3] = 0.0f;
        #pragma unroll 1
        for (int kb = 0; kb < 4; kb++) {
            uint32_t a0, a1, a2, a3;
            ldsm_x4(a0, a1, a2, a3, a_base + kb*32);
            const float* brow = sB2 + (kb*4 + q)*136 + g*2;
            #pragma unroll
            for (int nb = 0; nb < 8; nb++) {
                uint2 bv = *(const uint2*)(brow + nb*16);
                mma_f16(acc2[nb], a0, a1, a2, a3, bv.x, bv.y);
            }
        }
        // ---- epilogue 2: +rayBias(smem), half2 gelu, xW2 (fp32), reduce, sigmoid
        const int pA = pbase + m0 + g;
        const int pB = pA + 8;
        const float* biasA = sBiasB + (pA / NS - ray0) * 64;
        const float* biasB = sBiasB + (pB / NS - ray0) * 64;
        float rA0 = 0.f, rA1 = 0.f, rA2 = 0.f, rB0 = 0.f, rB1 = 0.f, rB2 = 0.f;
        #pragma unroll
        for (int nb = 0; nb < 8; nb++) {
            int c0 = nb*8 + 2*q, c1 = c0 + 1;
            __half2 gA = gelu_h2(__floats2half2_rn(acc2[nb][0] + biasA[c0],
                                                   acc2[nb][1] + biasA[c1]));
            __half2 gB = gelu_h2(__floats2half2_rn(acc2[nb][2] + biasB[c0],
                                                   acc2[nb][3] + biasB[c1]));
            float2 vA = __half22float2(gA);
            float2 vB = __half22float2(gB);
            float w00 = sW2[c0*3+0], w01 = sW2[c0*3+1], w02 = sW2[c0*3+2];
            float w10 = sW2[c1*3+0], w11 = sW2[c1*3+1], w12 = sW2[c1*3+2];
            rA0 += vA.x*w00 + vA.y*w10;
            rA1 += vA.x*w01 + vA.y*w11;
            rA2 += vA.x*w02 + vA.y*w12;
            rB0 += vB.x*w00 + vB.y*w10;
            rB1 += vB.x*w01 + vB.y*w11;
            rB2 += vB.x*w02 + vB.y*w12;
        }
        #pragma unroll
        for (int off = 1; off <= 2; off <<= 1) {
            rA0 += __shfl_xor_sync(0xffffffffu, rA0, off);
            rA1 += __shfl_xor_sync(0xffffffffu, rA1, off);
            rA2 += __shfl_xor_sync(0xffffffffu, rA2, off);
            rB0 += __shfl_xor_sync(0xffffffffu, rB0, off);
            rB1 += __shfl_xor_sync(0xffffffffu, rB1, off);
            rB2 += __shfl_xor_sync(0xffffffffu, rB2, off);
        }
        if (q == 0) {
            float c0 = b2[0], c1 = b2[1], c2 = b2[2];
            float* oA = g_rgb + (size_t)pA * 3;
            oA[0] = sigmoid_fast(rA0 + c0);
            oA[1] = sigmoid_fast(rA1 + c1);
            oA[2] = sigmoid_fast(rA2 + c2);
            float* oB = g_rgb + (size_t)pB * 3;
            oB[0] = sigmoid_fast(rB0 + c0);
            oB[1] = sigmoid_fast(rB1 + c1);
            oB[2] = sigmoid_fast(rB2 + c2);
        }
        // no trailing sync: next tile samples into the other buffer
    }
}

// ---------------- per-ray compositing ----------------
__global__ void k_render(float* __restrict__ out_rgb, float* __restrict__ out_depth,
                         float* __restrict__ w) {
    int qq = blockIdx.x * blockDim.x + threadIdx.x;
    if (qq >= NRAYS) return;
    float T = 1.0f, a0 = 0.0f, a1 = 0.0f, a2 = 0.0f, dep = 0.0f;
    const float* rp = g_rgb + (size_t)qq * NS * 3;
    float* wp = w + (size_t)qq * NS;
    #pragma unroll 1
    for (int s = 0; s < NS; s++) {
        float sg = wp[s];
        float al = 1.0f - __expf(-sg * DT);
        float wt = al * T;
        T *= (1.0f - al + 1e-10f);
        wp[s] = wt;
        dep += wt * (((float)s + 0.5f) * DT);
        a0 += wt * rp[s*3+0];
        a1 += wt * rp[s*3+1];
        a2 += wt * rp[s*3+2];
    }
    out_rgb[qq*3+0] = a0;
    out_rgb[qq*3+1] = a1;
    out_rgb[qq*3+2] = a2;
    out_depth[qq]   = dep;
}

// ---------------- launch ----------------
extern "C" void kernel_launch(void* const* d_in, const int* in_sizes, int n_in,
                              void* d_out, int out_size) {
    const float* rays_o  = (const float*)d_in[0];
    const float* rays_d  = (const float*)d_in[1];
    const float* matrixs = (const float*)d_in[2];
    const float* vectors = (const float*)d_in[3];
    const float* w_mat   = (const float*)d_in[4];
    const float* b_mat   = (const float*)d_in[5];
    const float* w1      = (const float*)d_in[6];
    const float* b1      = (const float*)d_in[7];
    const float* w2      = (const float*)d_in[8];
    const float* b2      = (const float*)d_in[9];

    float* out       = (float*)d_out;
    float* out_rgb   = out;
    float* out_depth = out + NRAYS*3;
    float* out_w     = out + NRAYS*4;

    static int nsm = 0;
    if (nsm == 0) {
        cudaDeviceProp prop;
        cudaGetDeviceProperties(&prop, 0);
        nsm = prop.multiProcessorCount;
        cudaFuncSetAttribute(k_fused, cudaFuncAttributeMaxDynamicSharedMemorySize,
                             SMEM_FLOATS * sizeof(float));
    }

    k_prep<<<(MATN + 255)/256, 256>>>(matrixs, vectors, rays_d, w1, b1);
    k_fused<<<2*nsm, 256, SMEM_FLOATS * sizeof(float)>>>(rays_o, rays_d, w_mat, b_mat,
                                                          w1, w2, b2, out_w);
    k_render<<<(NRAYS + 127)/128, 128>>>(out_rgb, out_depth, out_w);
}